// round 10
// baseline (speedup 1.0000x reference)
#include <cuda_runtime.h>
#include <cstdint>

// Pendulum2 constrained-dynamics RHS, closed form — FINAL.
// Best measured: 17.9-18.1us kernel / 21.0us harness, rel_err 1.3e-7,
// ~7.3 TB/s aggregate (DRAM+L2) ~= 90% of the sustained mixed-R/W LTS
// ceiling. Memory-roofline-bound; compute pipes <15%.
//
// Shape: one row (32B) per thread, Blackwell 256-bit ld/st
// (ld/st.global.v8.b32) -> each warp issues fully dense 1KB requests;
// 25 regs, block=256, occ ~74% (steady-state memory-limited residency).
//
// Measured and rejected across R1-R9:
//   - float4 pairs (R1: 19.4us), 64B/thread+.cs (R2: 24.3us),
//     2-stream MLP (R3: 20.1us), .cs stores (R5: 18.4us),
//     2 rows/thread v8 (R6: 18.9us), block 512 (R7: 18.5us),
//     block 128 (R9: 18.3us, occ unchanged -> residency is memory-set).
//
// Math (M0=M1=10, G=10), closed form replacing jacfwd/vmap/linalg.solve:
//   phi_q = [[2x0,2x1,0,0],[2dx,2dy,-2dx,-2dy]],  L = 0.4*[[s1,c],[c,2s2]]
//   det' = 2 s1 s2 - c^2 = s1 s2 + u^2  (u = x0 dy - x1 dx; Cauchy-Schwarz
//   identity -> cancellation-free, keeps rel_err ~1e-7 in the ill-conditioned
//   tail of the normal-random batch)
//   R1 = -20 x1 + 2|v01|^2 ; R2 = 2|dv|^2  (gravity row-2 term cancels)
//   lam = 2.5 * adj([[s1,c],[c,2s2]]) R / det' ;  a = (F - phi_q^T lam)/10

__global__ void __launch_bounds__(256)
pendulum2_kernel(const float* __restrict__ in, float* __restrict__ out, int bs)
{
    int i = blockIdx.x * blockDim.x + threadIdx.x;
    if (i >= bs) return;

    const float* p = in + 8u * (uint32_t)i;
    uint32_t r0, r1, r2, r3, r4, r5, r6, r7;
    asm("ld.global.v8.b32 {%0,%1,%2,%3,%4,%5,%6,%7}, [%8];"
        : "=r"(r0), "=r"(r1), "=r"(r2), "=r"(r3),
          "=r"(r4), "=r"(r5), "=r"(r6), "=r"(r7)
        : "l"(p));

    float x0 = __uint_as_float(r0), x1 = __uint_as_float(r1);
    float x2 = __uint_as_float(r2), x3 = __uint_as_float(r3);
    float v0 = __uint_as_float(r4), v1 = __uint_as_float(r5);
    float v2 = __uint_as_float(r6), v3 = __uint_as_float(r7);

    float dx  = x0 - x2;
    float dy  = x1 - x3;
    float dv0 = v0 - v2;
    float dv1 = v1 - v3;

    float s1 = fmaf(x0, x0, x1 * x1);
    float s2 = fmaf(dx, dx, dy * dy);
    float c  = fmaf(x0, dx, x1 * dy);
    float u  = fmaf(x0, dy, -(x1 * dx));

    float R1 = fmaf(2.0f, fmaf(v0, v0, v1 * v1), -20.0f * x1);
    float R2 = 2.0f * fmaf(dv0, dv0, dv1 * dv1);

    float det = fmaf(s1, s2, u * u);   // = 2*s1*s2 - c^2, stable form
    float inv = 2.5f / det;

    float lam1 = fmaf(2.0f * s2, R1, -(c * R2)) * inv;
    float lam2 = fmaf(s1, R2, -(c * R1)) * inv;

    float a0 = -0.2f * fmaf(x0, lam1, dx * lam2);
    float a1 = fmaf(-0.2f, fmaf(x1, lam1, dy * lam2), -10.0f);
    float a2 = 0.2f * (dx * lam2);
    float a3 = fmaf(0.2f, dy * lam2, -10.0f);

    float* q = out + 8u * (uint32_t)i;
    asm volatile("st.global.v8.b32 [%0], {%1,%2,%3,%4,%5,%6,%7,%8};"
                 :: "l"(q),
                    "r"(__float_as_uint(v0)), "r"(__float_as_uint(v1)),
                    "r"(__float_as_uint(v2)), "r"(__float_as_uint(v3)),
                    "r"(__float_as_uint(a0)), "r"(__float_as_uint(a1)),
                    "r"(__float_as_uint(a2)), "r"(__float_as_uint(a3))
                 : "memory");
}

extern "C" void kernel_launch(void* const* d_in, const int* in_sizes, int n_in,
                              void* d_out, int out_size)
{
    // inputs (metadata order): t (1,), coords (bs, 8)
    const float* coords = (const float*)d_in[1];
    int bs = in_sizes[1] / 8;

    int threads = 256;
    int blocks  = (bs + threads - 1) / threads;
    pendulum2_kernel<<<blocks, threads>>>(coords, (float*)d_out, bs);
}

// round 11
// speedup vs baseline: 1.1082x; 1.1082x over previous
#include <cuda_runtime.h>
#include <cstdint>

// Pendulum2 constrained-dynamics RHS, closed form — FINAL (unchanged from
// R8/R9/R10; those three runs are the same source and bracket harness noise:
// kernel stable at 17.9-18.3us, harness 20.99-23.26us, rel_err 1.308e-7).
//
// Roofline: streams 128 MiB/launch at ~7.3 TB/s aggregate (DRAM ~4.7 TB/s +
// L2 remainder) ~= the B300 path-independent LTS ceiling (~6300 B/cyc) for a
// 50/50 R/W stream. Compute pipes <15% busy — memory-bound by construction.
//
// Shape: one row (32B) per thread, Blackwell 256-bit ld/st
// (ld/st.global.v8.b32) -> each warp issues fully dense 1KB requests;
// 25 regs, block=256.
//
// Measured and rejected (R1-R9): float4 pairs (19.4us), 64B/thread+.cs
// (24.3us), 2-stream MLP (20.1us), .cs stores (18.4us), 2 rows/thread v8
// (18.9us), block 512 (18.5us), block 128 (18.3us, occ unchanged —
// residency is set by the memory system, not launch geometry).
//
// Math (M0=M1=10, G=10), closed form replacing jacfwd/vmap/linalg.solve:
//   phi_q = [[2x0,2x1,0,0],[2dx,2dy,-2dx,-2dy]],  L = 0.4*[[s1,c],[c,2s2]]
//   det' = 2 s1 s2 - c^2 = s1 s2 + u^2  (u = x0 dy - x1 dx; Cauchy-Schwarz
//   identity -> cancellation-free 2x2 solve)
//   R1 = -20 x1 + 2|v01|^2 ; R2 = 2|dv|^2  (gravity row-2 term cancels)
//   lam = 2.5 * adj([[s1,c],[c,2s2]]) R / det' ;  a = (F - phi_q^T lam)/10

__global__ void __launch_bounds__(256)
pendulum2_kernel(const float* __restrict__ in, float* __restrict__ out, int bs)
{
    int i = blockIdx.x * blockDim.x + threadIdx.x;
    if (i >= bs) return;

    const float* p = in + 8u * (uint32_t)i;
    uint32_t r0, r1, r2, r3, r4, r5, r6, r7;
    asm("ld.global.v8.b32 {%0,%1,%2,%3,%4,%5,%6,%7}, [%8];"
        : "=r"(r0), "=r"(r1), "=r"(r2), "=r"(r3),
          "=r"(r4), "=r"(r5), "=r"(r6), "=r"(r7)
        : "l"(p));

    float x0 = __uint_as_float(r0), x1 = __uint_as_float(r1);
    float x2 = __uint_as_float(r2), x3 = __uint_as_float(r3);
    float v0 = __uint_as_float(r4), v1 = __uint_as_float(r5);
    float v2 = __uint_as_float(r6), v3 = __uint_as_float(r7);

    float dx  = x0 - x2;
    float dy  = x1 - x3;
    float dv0 = v0 - v2;
    float dv1 = v1 - v3;

    float s1 = fmaf(x0, x0, x1 * x1);
    float s2 = fmaf(dx, dx, dy * dy);
    float c  = fmaf(x0, dx, x1 * dy);
    float u  = fmaf(x0, dy, -(x1 * dx));

    float R1 = fmaf(2.0f, fmaf(v0, v0, v1 * v1), -20.0f * x1);
    float R2 = 2.0f * fmaf(dv0, dv0, dv1 * dv1);

    float det = fmaf(s1, s2, u * u);   // = 2*s1*s2 - c^2, stable form
    float inv = 2.5f / det;

    float lam1 = fmaf(2.0f * s2, R1, -(c * R2)) * inv;
    float lam2 = fmaf(s1, R2, -(c * R1)) * inv;

    float a0 = -0.2f * fmaf(x0, lam1, dx * lam2);
    float a1 = fmaf(-0.2f, fmaf(x1, lam1, dy * lam2), -10.0f);
    float a2 = 0.2f * (dx * lam2);
    float a3 = fmaf(0.2f, dy * lam2, -10.0f);

    float* q = out + 8u * (uint32_t)i;
    asm volatile("st.global.v8.b32 [%0], {%1,%2,%3,%4,%5,%6,%7,%8};"
                 :: "l"(q),
                    "r"(__float_as_uint(v0)), "r"(__float_as_uint(v1)),
                    "r"(__float_as_uint(v2)), "r"(__float_as_uint(v3)),
                    "r"(__float_as_uint(a0)), "r"(__float_as_uint(a1)),
                    "r"(__float_as_uint(a2)), "r"(__float_as_uint(a3))
                 : "memory");
}

extern "C" void kernel_launch(void* const* d_in, const int* in_sizes, int n_in,
                              void* d_out, int out_size)
{
    // inputs (metadata order): t (1,), coords (bs, 8)
    const float* coords = (const float*)d_in[1];
    int bs = in_sizes[1] / 8;

    int threads = 256;
    int blocks  = (bs + threads - 1) / threads;
    pendulum2_kernel<<<blocks, threads>>>(coords, (float*)d_out, bs);
}